// round 14
// baseline (speedup 1.0000x reference)
#include <cuda_runtime.h>
#include <cstdint>
#include <math.h>

#define HIDDEN   2048
#define NQ       8
#define HD       256
#define QKV_ROWS 2560   // (8 + 2) * 256
#define SEQ      8192
#define LAYER    5
#define CHUNK    32
#define NCHUNK   256    // SEQ / CHUNK
#define DEPTH    8
#define STAGE_BYTES 16384                  // 2 rows * 2048 f32
#define GEMV_SMEM (DEPTH * STAGE_BYTES + DEPTH * 8)
#define GEMV_GRID 148

// ---------------- scratch (device globals; no allocation) ----------------
__device__ __align__(16) float g_qkv[QKV_ROWS];
__device__ __align__(16) float g_part[NCHUNK * NQ * HD];
__device__ __align__(16) float g_l[NCHUNK * NQ];
__device__ __align__(16) float g_attn[NQ * HD];

__device__ __forceinline__ float warp_sum(float v) {
#pragma unroll
    for (int o = 16; o; o >>= 1) v += __shfl_xor_sync(0xffffffffu, v, o);
    return v;
}
__device__ __forceinline__ float warp_max(float v) {
#pragma unroll
    for (int o = 16; o; o >>= 1) v = fmaxf(v, __shfl_xor_sync(0xffffffffu, v, o));
    return v;
}
__device__ __forceinline__ float dot4(float4 a, float4 b) {
    return a.x * b.x + a.y * b.y + a.z * b.z + a.w * b.w;
}
__device__ __forceinline__ void mbar_wait(uint32_t bar, int parity) {
    asm volatile(
        "{\n\t.reg .pred P;\n\t"
        "WAIT_%=:\n\t"
        "mbarrier.try_wait.parity.acquire.cta.shared::cta.b64 P, [%0], %1, 0x989680;\n\t"
        "@P bra.uni DONE_%=;\n\t"
        "bra.uni WAIT_%=;\n\t"
        "DONE_%=:\n\t}"
        :: "r"(bar), "r"(parity) : "memory");
}
__device__ __forceinline__ void bulk_copy(uint32_t dst, const float* src,
                                          uint32_t bar) {
    asm volatile("mbarrier.arrive.expect_tx.shared.b64 _, [%0], %1;"
                 :: "r"(bar), "r"(STAGE_BYTES) : "memory");
    asm volatile("cp.async.bulk.shared::cta.global.mbarrier::complete_tx::bytes "
                 "[%0], [%1], %2, [%3];"
                 :: "r"(dst), "l"(src), "r"(STAGE_BYTES), "r"(bar) : "memory");
}

// ---------------- TMA-pipelined GEMV ----------------------------------------
// Persistent: 148 blocks, each grid-strides over row-pairs. 8-deep ring of
// 16KB stages filled by cp.async.bulk (bypasses the per-SM L1tex MSHR cap
// that pinned all LDG variants at ~2.5 TB/s). x lives in 4 registers.
__global__ void __launch_bounds__(256, 1)
gemv_tma_kernel(const float* __restrict__ W,
                const float* __restrict__ x,
                float* __restrict__ y, int nPairs) {
    extern __shared__ __align__(16) char dsm[];
    float4*  stg      = reinterpret_cast<float4*>(dsm);
    uint32_t stg_base = (uint32_t)__cvta_generic_to_shared(dsm);
    uint32_t bar_base = stg_base + DEPTH * STAGE_BYTES;
    __shared__ float swarp[2][8];

    int tid  = threadIdx.x;
    int bid  = blockIdx.x;
    int G    = gridDim.x;
    int warp = tid >> 5, lane = tid & 31;
    int rl   = tid >> 7;          // row within pair
    int t    = tid & 127;         // thread within row

    if (tid == 0) {
#pragma unroll
        for (int s = 0; s < DEPTH; s++)
            asm volatile("mbarrier.init.shared.b64 [%0], 1;"
                         :: "r"(bar_base + s * 8) : "memory");
    }
    __syncthreads();

    int count = (nPairs - bid + G - 1) / G;      // stages for this block

    if (tid == 0) {
        int pre = count < DEPTH ? count : DEPTH;
        for (int i = 0; i < pre; i++)
            bulk_copy(stg_base + i * STAGE_BYTES,
                      W + (size_t)(bid + (size_t)i * G) * 4096,
                      bar_base + i * 8);
    }

    // x is identical for every stage: hold in registers (load overlaps fills)
    const float4* x4 = reinterpret_cast<const float4*>(x);
    float4 v0 = __ldg(&x4[t]);
    float4 v1 = __ldg(&x4[t + 128]);
    float4 v2 = __ldg(&x4[t + 256]);
    float4 v3 = __ldg(&x4[t + 384]);

    for (int i = 0; i < count; i++) {
        int slot   = i & (DEPTH - 1);
        int parity = (i / DEPTH) & 1;
        mbar_wait(bar_base + slot * 8, parity);

        const float4* buf = stg + slot * 1024 + rl * 512;
        float acc = dot4(buf[t],       v0) + dot4(buf[t + 128], v1)
                  + dot4(buf[t + 256], v2) + dot4(buf[t + 384], v3);
        acc = warp_sum(acc);
        if (lane == 0) swarp[i & 1][warp] = acc;
        __syncthreads();          // stage consumed + swarp visible

        int rp = bid + i * G;
        if (tid < 2)
            y[rp * 2 + tid] = swarp[i & 1][4 * tid]     + swarp[i & 1][4 * tid + 1]
                            + swarp[i & 1][4 * tid + 2] + swarp[i & 1][4 * tid + 3];
        if (tid == 0 && i + DEPTH < count)
            bulk_copy(stg_base + slot * STAGE_BYTES,
                      W + (size_t)(bid + (size_t)(i + DEPTH) * G) * 4096,
                      bar_base + slot * 8);
    }
}

// ---------------- fused attention (512 threads, R12 config) -----------------
__global__ void __launch_bounds__(512, 2)
fused_attn_kernel(const float* __restrict__ kc,
                  const float* __restrict__ vc,
                  const float* __restrict__ mask,
                  const float* __restrict__ cosv,
                  const float* __restrict__ sinv,
                  const float* __restrict__ qw,
                  const float* __restrict__ kw,
                  const int* __restrict__ kvidx) {
    __shared__ float sq[NQ * HD];
    __shared__ float sk[HD];
    __shared__ float sexp[CHUNK * NQ];
    __shared__ float smask[CHUNK];
    __shared__ float sup[NQ][HD];
    __shared__ int   sany;

    int c    = blockIdx.x;
    int tid  = threadIdx.x;
    int warp = tid >> 5, lane = tid & 31;
    int s0   = c * CHUNK;

    if (tid == 0) sany = 0;
    __syncthreads();
    if (tid < CHUNK) {
        float m = mask[s0 + tid];
        smask[tid] = m;
        if (m > -1e8f) atomicOr(&sany, 1);
    }
    __syncthreads();
    if (!sany) {
        if (tid < NQ) g_l[c * NQ + tid] = 0.0f;
        return;
    }

    if (warp < 9) {
        int head = warp;
        float x[8];
#pragma unroll
        for (int j = 0; j < 8; j++) x[j] = g_qkv[head * HD + lane + 32 * j];
        float mv = 0.f;
#pragma unroll
        for (int j = 0; j < 8; j++) mv = fmaxf(mv, fabsf(x[j]));
        mv = warp_max(mv);
        mv = fmaxf(mv, 5.9604644775390625e-8f);   // 2^-24
        float ss = 0.f, xs[8];
#pragma unroll
        for (int j = 0; j < 8; j++) { xs[j] = x[j] / mv; ss += xs[j] * xs[j]; }
        ss = warp_sum(ss);
        float rs = rsqrtf(ss);
        const float* wv = (head < NQ) ? qw : kw;
        float y[8];
#pragma unroll
        for (int j = 0; j < 8; j++) {
            int d = lane + 32 * j;
            y[j] = rs * 16.0f * xs[j] * (1.0f + wv[d]);
        }
#pragma unroll
        for (int j = 0; j < 8; j++) {
            int d = lane + 32 * j;
            float rot = (j < 4) ? -y[j ^ 4] : y[j ^ 4];
            float out = y[j] * cosv[d] + rot * sinv[d];
            if (head < NQ) sq[head * HD + d] = out * 0.0625f;  // * 256^-0.5
            else           sk[d] = out;
        }
    }
    __syncthreads();

    int pos = *kvidx;
    const float* kbase = kc + (size_t)LAYER * SEQ * HD;

    {
        float acc[2][NQ];
        const float4* k4p[2];
#pragma unroll
        for (int r = 0; r < 2; r++) {
            int sl = warp * 2 + r;
            int s = s0 + sl;
            const float* krow = (s == pos) ? sk : (kbase + (size_t)s * HD);
            k4p[r] = reinterpret_cast<const float4*>(krow);
#pragma unroll
            for (int h = 0; h < NQ; h++) acc[r][h] = 0.f;
        }
#pragma unroll
        for (int i = 0; i < 2; i++) {
            int idx = i * 32 + lane;
            float4 kv0 = k4p[0][idx];
            float4 kv1 = k4p[1][idx];
#pragma unroll
            for (int h = 0; h < NQ; h++) {
                const float4* q4 = reinterpret_cast<const float4*>(&sq[h * HD]);
                float4 qv = q4[idx];
                acc[0][h] += dot4(kv0, qv);
                acc[1][h] += dot4(kv1, qv);
            }
        }
#pragma unroll
        for (int r = 0; r < 2; r++) {
            int sl = warp * 2 + r;
            float m = smask[sl];
#pragma unroll
            for (int h = 0; h < NQ; h++) {
                float v = warp_sum(acc[r][h]);
                if (lane == h)
                    sexp[sl * NQ + h] = (m < -1e8f) ? 0.0f
                                      : expf(tanhf(v * 0.02f) * 50.0f + m);
            }
        }
    }
    __syncthreads();

    if (warp < NQ) {
        float l = sexp[lane * NQ + warp];
        l = warp_sum(l);
        if (lane == 0) g_l[c * NQ + warp] = l;
    }

    const float* vbase = vc + (size_t)LAYER * SEQ * HD;
    const float* vnew  = g_qkv + 9 * HD;
    int grp = tid >> 8;
    int d   = tid & 255;
    float acc[NQ] = {0, 0, 0, 0, 0, 0, 0, 0};
#pragma unroll 8
    for (int k = 0; k < CHUNK / 2; k++) {
        int sl = grp * (CHUNK / 2) + k;
        int s = s0 + sl;
        float v = (s == pos) ? vnew[d] : __ldcs(&vbase[(size_t)s * HD + d]);
#pragma unroll
        for (int h = 0; h < NQ; h++) acc[h] += sexp[sl * NQ + h] * v;
    }
    if (grp == 1) {
#pragma unroll
        for (int h = 0; h < NQ; h++) sup[h][d] = acc[h];
    }
    __syncthreads();
    if (grp == 0) {
#pragma unroll
        for (int h = 0; h < NQ; h++)
            g_part[(c * NQ + h) * HD + d] = acc[h] + sup[h][d];
    }
}

// ---------------- combine partials across chunks ---------------------------
__global__ void combine_kernel() {
    int h  = blockIdx.x;
    int d0 = blockIdx.y * 32;
    int tid = threadIdx.x;
    int g  = tid >> 5;
    int dl = tid & 31;
    int d  = d0 + dl;

    __shared__ float sl[NCHUNK];
    sl[tid] = g_l[tid * NQ + h];
    __syncthreads();

    float acc = 0.f, L = 0.f;
#pragma unroll
    for (int k = 0; k < 32; k++) {
        int c = g * 32 + k;
        float l = sl[c];
        if (l > 0.f) {
            L += l;
            acc += g_part[(c * NQ + h) * HD + d];
        }
    }
    __shared__ float sacc[8][32];
    __shared__ float sLr[8][32];
    sacc[g][dl] = acc;
    sLr[g][dl]  = L;
    __syncthreads();
    if (g == 0) {
        float a = 0.f, Lt = 0.f;
#pragma unroll
        for (int k = 0; k < 8; k++) { a += sacc[k][dl]; Lt += sLr[k][dl]; }
        g_attn[h * HD + d] = a / Lt;
    }
}

// ---------------- launch ----------------------------------------------------
extern "C" void kernel_launch(void* const* d_in, const int* in_sizes, int n_in,
                              void* d_out, int out_size) {
    const float* hs   = (const float*)d_in[0];   // hidden_states (2048)
    const float* cosv = (const float*)d_in[1];   // cos (256)
    const float* sinv = (const float*)d_in[2];   // sin (256)
    const int*   kvix = (const int*)  d_in[3];   // kv_write_indices (1)
    const float* kc   = (const float*)d_in[4];   // k_cache
    const float* vc   = (const float*)d_in[5];   // v_cache
    const float* mask = (const float*)d_in[6];   // mask (8192)
    const float* qkvw = (const float*)d_in[7];   // qkv_w (2560x2048)
    const float* ow   = (const float*)d_in[8];   // o_w   (2048x2048)
    const float* qnw  = (const float*)d_in[9];   // q_norm_w (256)
    const float* knw  = (const float*)d_in[10];  // k_norm_w (256)
    float* out = (float*)d_out;

    void* p_qkv = nullptr;
    void* p_attn = nullptr;
    cudaGetSymbolAddress(&p_qkv, g_qkv);
    cudaGetSymbolAddress(&p_attn, g_attn);

    cudaFuncSetAttribute(gemv_tma_kernel,
                         cudaFuncAttributeMaxDynamicSharedMemorySize, GEMV_SMEM);

    gemv_tma_kernel<<<GEMV_GRID, 256, GEMV_SMEM>>>(qkvw, hs, (float*)p_qkv,
                                                   QKV_ROWS / 2);
    fused_attn_kernel<<<NCHUNK, 512>>>(kc, vc, mask, cosv, sinv, qnw, knw, kvix);
    combine_kernel<<<dim3(NQ, 8), 256>>>();
    gemv_tma_kernel<<<GEMV_GRID, 256, GEMV_SMEM>>>(ow, (const float*)p_attn, out,
                                                   HIDDEN / 2);
}

// round 15
// speedup vs baseline: 1.2871x; 1.2871x over previous
#include <cuda_runtime.h>
#include <cstdint>
#include <math.h>

#define HIDDEN   2048
#define NQ       8
#define HD       256
#define QKV_ROWS 2560   // (8 + 2) * 256
#define SEQ      8192
#define LAYER    5
#define CHUNK    32
#define NCHUNK   256    // SEQ / CHUNK
#define GW_GRID  148

// ---------------- scratch (device globals; no allocation) ----------------
__device__ __align__(16) float g_qkv[QKV_ROWS];
__device__ __align__(16) float g_part[NCHUNK * NQ * HD];
__device__ __align__(16) float g_l[NCHUNK * NQ];
__device__ __align__(16) float g_attn[NQ * HD];

__device__ __forceinline__ float warp_sum(float v) {
#pragma unroll
    for (int o = 16; o; o >>= 1) v += __shfl_xor_sync(0xffffffffu, v, o);
    return v;
}
__device__ __forceinline__ float warp_max(float v) {
#pragma unroll
    for (int o = 16; o; o >>= 1) v = fmaxf(v, __shfl_xor_sync(0xffffffffu, v, o));
    return v;
}
__device__ __forceinline__ float dot4(float4 a, float4 b) {
    return a.x * b.x + a.y * b.y + a.z * b.z + a.w * b.w;
}

// ---------------- warp-autonomous persistent GEMV --------------------------
// 148 blocks x 8 warps; warp-per-row, grid-strided. Next row's halves are
// prefetched into registers while the current row is dotted/reduced, and
// there are NO block syncs in the loop -> each warp keeps 8-16 cache lines
// in flight continuously; 8 warps/SM saturate the per-SM MSHR cap with
// ~full duty (vs ~70% for one-shot blocks).
__global__ void __launch_bounds__(256)
gemv_kernel(const float* __restrict__ W,
            const float* __restrict__ x,
            float* __restrict__ y, int rows) {
    __shared__ float4 sx[HIDDEN / 4];
    int tid  = threadIdx.x;
    int lane = tid & 31;
    const float4* x4 = reinterpret_cast<const float4*>(x);
    sx[tid]       = __ldg(&x4[tid]);
    sx[tid + 256] = __ldg(&x4[tid + 256]);
    __syncthreads();                 // only sync in the kernel

    int gw = blockIdx.x * 8 + (tid >> 5);   // global warp id
    int nw = gridDim.x * 8;                 // 1184 warps

    float4 A[8], B[8];
    int r = gw;
    if (r < rows) {
        const float4* Wr = reinterpret_cast<const float4*>(W + (size_t)r * HIDDEN);
#pragma unroll
        for (int k = 0; k < 8; k++) A[k] = __ldcs(&Wr[lane + 32 * k]);
#pragma unroll
        for (int k = 0; k < 8; k++) B[k] = __ldcs(&Wr[256 + lane + 32 * k]);
    }
    while (r < rows) {
        int rn = r + nw;
        const float4* Wn = reinterpret_cast<const float4*>(W + (size_t)rn * HIDDEN);

        float acc = 0.f;
#pragma unroll
        for (int k = 0; k < 8; k++) acc += dot4(A[k], sx[lane + 32 * k]);

        // prefetch next row (first half) while second half is reduced
        if (rn < rows) {
#pragma unroll
            for (int k = 0; k < 8; k++) A[k] = __ldcs(&Wn[lane + 32 * k]);
        }
#pragma unroll
        for (int k = 0; k < 8; k++) acc += dot4(B[k], sx[256 + lane + 32 * k]);
        if (rn < rows) {
#pragma unroll
            for (int k = 0; k < 8; k++) B[k] = __ldcs(&Wn[256 + lane + 32 * k]);
        }

        acc = warp_sum(acc);
        if (lane == 0) y[r] = acc;
        r = rn;
    }
}

// ---------------- fused attention (512 threads, R12 config — proven) -------
__global__ void __launch_bounds__(512, 2)
fused_attn_kernel(const float* __restrict__ kc,
                  const float* __restrict__ vc,
                  const float* __restrict__ mask,
                  const float* __restrict__ cosv,
                  const float* __restrict__ sinv,
                  const float* __restrict__ qw,
                  const float* __restrict__ kw,
                  const int* __restrict__ kvidx) {
    __shared__ float sq[NQ * HD];
    __shared__ float sk[HD];
    __shared__ float sexp[CHUNK * NQ];
    __shared__ float smask[CHUNK];
    __shared__ float sup[NQ][HD];
    __shared__ int   sany;

    int c    = blockIdx.x;
    int tid  = threadIdx.x;
    int warp = tid >> 5, lane = tid & 31;
    int s0   = c * CHUNK;

    if (tid == 0) sany = 0;
    __syncthreads();
    if (tid < CHUNK) {
        float m = mask[s0 + tid];
        smask[tid] = m;
        if (m > -1e8f) atomicOr(&sany, 1);
    }
    __syncthreads();
    if (!sany) {
        if (tid < NQ) g_l[c * NQ + tid] = 0.0f;
        return;
    }

    if (warp < 9) {
        int head = warp;
        float x[8];
#pragma unroll
        for (int j = 0; j < 8; j++) x[j] = g_qkv[head * HD + lane + 32 * j];
        float mv = 0.f;
#pragma unroll
        for (int j = 0; j < 8; j++) mv = fmaxf(mv, fabsf(x[j]));
        mv = warp_max(mv);
        mv = fmaxf(mv, 5.9604644775390625e-8f);   // 2^-24
        float ss = 0.f, xs[8];
#pragma unroll
        for (int j = 0; j < 8; j++) { xs[j] = x[j] / mv; ss += xs[j] * xs[j]; }
        ss = warp_sum(ss);
        float rs = rsqrtf(ss);
        const float* wv = (head < NQ) ? qw : kw;
        float y[8];
#pragma unroll
        for (int j = 0; j < 8; j++) {
            int d = lane + 32 * j;
            y[j] = rs * 16.0f * xs[j] * (1.0f + wv[d]);
        }
#pragma unroll
        for (int j = 0; j < 8; j++) {
            int d = lane + 32 * j;
            float rot = (j < 4) ? -y[j ^ 4] : y[j ^ 4];
            float out = y[j] * cosv[d] + rot * sinv[d];
            if (head < NQ) sq[head * HD + d] = out * 0.0625f;  // * 256^-0.5
            else           sk[d] = out;
        }
    }
    __syncthreads();

    int pos = *kvidx;
    const float* kbase = kc + (size_t)LAYER * SEQ * HD;

    {
        float acc[2][NQ];
        const float4* k4p[2];
#pragma unroll
        for (int r = 0; r < 2; r++) {
            int sl = warp * 2 + r;
            int s = s0 + sl;
            const float* krow = (s == pos) ? sk : (kbase + (size_t)s * HD);
            k4p[r] = reinterpret_cast<const float4*>(krow);
#pragma unroll
            for (int h = 0; h < NQ; h++) acc[r][h] = 0.f;
        }
#pragma unroll
        for (int i = 0; i < 2; i++) {
            int idx = i * 32 + lane;
            float4 kv0 = k4p[0][idx];
            float4 kv1 = k4p[1][idx];
#pragma unroll
            for (int h = 0; h < NQ; h++) {
                const float4* q4 = reinterpret_cast<const float4*>(&sq[h * HD]);
                float4 qv = q4[idx];
                acc[0][h] += dot4(kv0, qv);
                acc[1][h] += dot4(kv1, qv);
            }
        }
#pragma unroll
        for (int r = 0; r < 2; r++) {
            int sl = warp * 2 + r;
            float m = smask[sl];
#pragma unroll
            for (int h = 0; h < NQ; h++) {
                float v = warp_sum(acc[r][h]);
                if (lane == h)
                    sexp[sl * NQ + h] = (m < -1e8f) ? 0.0f
                                      : expf(tanhf(v * 0.02f) * 50.0f + m);
            }
        }
    }
    __syncthreads();

    if (warp < NQ) {
        float l = sexp[lane * NQ + warp];
        l = warp_sum(l);
        if (lane == 0) g_l[c * NQ + warp] = l;
    }

    const float* vbase = vc + (size_t)LAYER * SEQ * HD;
    const float* vnew  = g_qkv + 9 * HD;
    int grp = tid >> 8;
    int d   = tid & 255;
    float acc[NQ] = {0, 0, 0, 0, 0, 0, 0, 0};
#pragma unroll 8
    for (int k = 0; k < CHUNK / 2; k++) {
        int sl = grp * (CHUNK / 2) + k;
        int s = s0 + sl;
        float v = (s == pos) ? vnew[d] : __ldcs(&vbase[(size_t)s * HD + d]);
#pragma unroll
        for (int h = 0; h < NQ; h++) acc[h] += sexp[sl * NQ + h] * v;
    }
    if (grp == 1) {
#pragma unroll
        for (int h = 0; h < NQ; h++) sup[h][d] = acc[h];
    }
    __syncthreads();
    if (grp == 0) {
#pragma unroll
        for (int h = 0; h < NQ; h++)
            g_part[(c * NQ + h) * HD + d] = acc[h] + sup[h][d];
    }
}

// ---------------- combine partials across chunks ---------------------------
__global__ void combine_kernel() {
    int h  = blockIdx.x;
    int d0 = blockIdx.y * 32;
    int tid = threadIdx.x;
    int g  = tid >> 5;
    int dl = tid & 31;
    int d  = d0 + dl;

    __shared__ float sl[NCHUNK];
    sl[tid] = g_l[tid * NQ + h];
    __syncthreads();

    float acc = 0.f, L = 0.f;
#pragma unroll
    for (int k = 0; k < 32; k++) {
        int c = g * 32 + k;
        float l = sl[c];
        if (l > 0.f) {
            L += l;
            acc += g_part[(c * NQ + h) * HD + d];
        }
    }
    __shared__ float sacc[8][32];
    __shared__ float sLr[8][32];
    sacc[g][dl] = acc;
    sLr[g][dl]  = L;
    __syncthreads();
    if (g == 0) {
        float a = 0.f, Lt = 0.f;
#pragma unroll
        for (int k = 0; k < 8; k++) { a += sacc[k][dl]; Lt += sLr[k][dl]; }
        g_attn[h * HD + d] = a / Lt;
    }
}

// ---------------- launch ----------------------------------------------------
extern "C" void kernel_launch(void* const* d_in, const int* in_sizes, int n_in,
                              void* d_out, int out_size) {
    const float* hs   = (const float*)d_in[0];   // hidden_states (2048)
    const float* cosv = (const float*)d_in[1];   // cos (256)
    const float* sinv = (const float*)d_in[2];   // sin (256)
    const int*   kvix = (const int*)  d_in[3];   // kv_write_indices (1)
    const float* kc   = (const float*)d_in[4];   // k_cache
    const float* vc   = (const float*)d_in[5];   // v_cache
    const float* mask = (const float*)d_in[6];   // mask (8192)
    const float* qkvw = (const float*)d_in[7];   // qkv_w (2560x2048)
    const float* ow   = (const float*)d_in[8];   // o_w   (2048x2048)
    const float* qnw  = (const float*)d_in[9];   // q_norm_w (256)
    const float* knw  = (const float*)d_in[10];  // k_norm_w (256)
    float* out = (float*)d_out;

    void* p_qkv = nullptr;
    void* p_attn = nullptr;
    cudaGetSymbolAddress(&p_qkv, g_qkv);
    cudaGetSymbolAddress(&p_attn, g_attn);

    gemv_kernel<<<GW_GRID, 256>>>(qkvw, hs, (float*)p_qkv, QKV_ROWS);
    fused_attn_kernel<<<NCHUNK, 512>>>(kc, vc, mask, cosv, sinv, qnw, knw, kvix);
    combine_kernel<<<dim3(NQ, 8), 256>>>();
    gemv_kernel<<<GW_GRID, 256>>>(ow, (const float*)p_attn, out, HIDDEN);
}

// round 16
// speedup vs baseline: 1.4009x; 1.0884x over previous
#include <cuda_runtime.h>
#include <cstdint>
#include <math.h>

#define HIDDEN   2048
#define NQ       8
#define HD       256
#define QKV_ROWS 2560   // (8 + 2) * 256
#define SEQ      8192
#define LAYER    5
#define CHUNK    32
#define NCHUNK   256    // SEQ / CHUNK

// ---------------- scratch (device globals; no allocation) ----------------
__device__ __align__(16) float g_qkv[QKV_ROWS];
__device__ __align__(16) float g_part[NCHUNK * NQ * HD];
__device__ __align__(16) float g_l[NCHUNK * NQ];
__device__ __align__(16) float g_attn[NQ * HD];

__device__ __forceinline__ float warp_sum(float v) {
#pragma unroll
    for (int o = 16; o; o >>= 1) v += __shfl_xor_sync(0xffffffffu, v, o);
    return v;
}
__device__ __forceinline__ float warp_max(float v) {
#pragma unroll
    for (int o = 16; o; o >>= 1) v = fmaxf(v, __shfl_xor_sync(0xffffffffu, v, o));
    return v;
}
__device__ __forceinline__ float dot4(float4 a, float4 b) {
    return a.x * b.x + a.y * b.y + a.z * b.z + a.w * b.w;
}

// ---------------- GEMV: 1 row / 128-thread block ----------------------------
// Many small independent blocks (12-16 co-resident per SM) keep the per-SM
// MSHR pool continuously occupied across block bursts (the one-shot
// 256-thread config idles the MSHRs during reduce/store/exit tails).
__global__ void __launch_bounds__(128)
gemv_kernel(const float* __restrict__ W,
            const float* __restrict__ x,
            float* __restrict__ y) {
    int t = threadIdx.x;            // 0..127
    int row = blockIdx.x;
    const float4* Wr = reinterpret_cast<const float4*>(W + (size_t)row * HIDDEN);
    const float4* x4 = reinterpret_cast<const float4*>(x);

    float4 w0 = __ldcs(&Wr[t]);
    float4 w1 = __ldcs(&Wr[t + 128]);
    float4 w2 = __ldcs(&Wr[t + 256]);
    float4 w3 = __ldcs(&Wr[t + 384]);
    float4 v0 = __ldg(&x4[t]);
    float4 v1 = __ldg(&x4[t + 128]);
    float4 v2 = __ldg(&x4[t + 256]);
    float4 v3 = __ldg(&x4[t + 384]);

    float acc = dot4(w0, v0) + dot4(w1, v1) + dot4(w2, v2) + dot4(w3, v3);
    acc = warp_sum(acc);

    __shared__ float swarp[4];
    int warp = t >> 5, lane = t & 31;
    if (lane == 0) swarp[warp] = acc;
    __syncthreads();
    if (t == 0)
        y[row] = swarp[0] + swarp[1] + swarp[2] + swarp[3];
}

// ---------------- fused attention (512 threads, R12 config — proven) -------
__global__ void __launch_bounds__(512, 2)
fused_attn_kernel(const float* __restrict__ kc,
                  const float* __restrict__ vc,
                  const float* __restrict__ mask,
                  const float* __restrict__ cosv,
                  const float* __restrict__ sinv,
                  const float* __restrict__ qw,
                  const float* __restrict__ kw,
                  const int* __restrict__ kvidx) {
    __shared__ float sq[NQ * HD];
    __shared__ float sk[HD];
    __shared__ float sexp[CHUNK * NQ];
    __shared__ float smask[CHUNK];
    __shared__ float sup[NQ][HD];
    __shared__ int   sany;

    int c    = blockIdx.x;
    int tid  = threadIdx.x;
    int warp = tid >> 5, lane = tid & 31;
    int s0   = c * CHUNK;

    if (tid == 0) sany = 0;
    __syncthreads();
    if (tid < CHUNK) {
        float m = mask[s0 + tid];
        smask[tid] = m;
        if (m > -1e8f) atomicOr(&sany, 1);
    }
    __syncthreads();
    if (!sany) {
        if (tid < NQ) g_l[c * NQ + tid] = 0.0f;
        return;
    }

    if (warp < 9) {
        int head = warp;
        float x[8];
#pragma unroll
        for (int j = 0; j < 8; j++) x[j] = g_qkv[head * HD + lane + 32 * j];
        float mv = 0.f;
#pragma unroll
        for (int j = 0; j < 8; j++) mv = fmaxf(mv, fabsf(x[j]));
        mv = warp_max(mv);
        mv = fmaxf(mv, 5.9604644775390625e-8f);   // 2^-24
        float ss = 0.f, xs[8];
#pragma unroll
        for (int j = 0; j < 8; j++) { xs[j] = x[j] / mv; ss += xs[j] * xs[j]; }
        ss = warp_sum(ss);
        float rs = rsqrtf(ss);
        const float* wv = (head < NQ) ? qw : kw;
        float y[8];
#pragma unroll
        for (int j = 0; j < 8; j++) {
            int d = lane + 32 * j;
            y[j] = rs * 16.0f * xs[j] * (1.0f + wv[d]);
        }
#pragma unroll
        for (int j = 0; j < 8; j++) {
            int d = lane + 32 * j;
            float rot = (j < 4) ? -y[j ^ 4] : y[j ^ 4];
            float out = y[j] * cosv[d] + rot * sinv[d];
            if (head < NQ) sq[head * HD + d] = out * 0.0625f;  // * 256^-0.5
            else           sk[d] = out;
        }
    }
    __syncthreads();

    int pos = *kvidx;
    const float* kbase = kc + (size_t)LAYER * SEQ * HD;

    {
        float acc[2][NQ];
        const float4* k4p[2];
#pragma unroll
        for (int r = 0; r < 2; r++) {
            int sl = warp * 2 + r;
            int s = s0 + sl;
            const float* krow = (s == pos) ? sk : (kbase + (size_t)s * HD);
            k4p[r] = reinterpret_cast<const float4*>(krow);
#pragma unroll
            for (int h = 0; h < NQ; h++) acc[r][h] = 0.f;
        }
#pragma unroll
        for (int i = 0; i < 2; i++) {
            int idx = i * 32 + lane;
            float4 kv0 = k4p[0][idx];
            float4 kv1 = k4p[1][idx];
#pragma unroll
            for (int h = 0; h < NQ; h++) {
                const float4* q4 = reinterpret_cast<const float4*>(&sq[h * HD]);
                float4 qv = q4[idx];
                acc[0][h] += dot4(kv0, qv);
                acc[1][h] += dot4(kv1, qv);
            }
        }
#pragma unroll
        for (int r = 0; r < 2; r++) {
            int sl = warp * 2 + r;
            float m = smask[sl];
#pragma unroll
            for (int h = 0; h < NQ; h++) {
                float v = warp_sum(acc[r][h]);
                if (lane == h)
                    sexp[sl * NQ + h] = (m < -1e8f) ? 0.0f
                                      : expf(tanhf(v * 0.02f) * 50.0f + m);
            }
        }
    }
    __syncthreads();

    if (warp < NQ) {
        float l = sexp[lane * NQ + warp];
        l = warp_sum(l);
        if (lane == 0) g_l[c * NQ + warp] = l;
    }

    const float* vbase = vc + (size_t)LAYER * SEQ * HD;
    const float* vnew  = g_qkv + 9 * HD;
    int grp = tid >> 8;
    int d   = tid & 255;
    float acc[NQ] = {0, 0, 0, 0, 0, 0, 0, 0};
#pragma unroll 8
    for (int k = 0; k < CHUNK / 2; k++) {
        int sl = grp * (CHUNK / 2) + k;
        int s = s0 + sl;
        float v = (s == pos) ? vnew[d] : __ldcs(&vbase[(size_t)s * HD + d]);
#pragma unroll
        for (int h = 0; h < NQ; h++) acc[h] += sexp[sl * NQ + h] * v;
    }
    if (grp == 1) {
#pragma unroll
        for (int h = 0; h < NQ; h++) sup[h][d] = acc[h];
    }
    __syncthreads();
    if (grp == 0) {
#pragma unroll
        for (int h = 0; h < NQ; h++)
            g_part[(c * NQ + h) * HD + d] = acc[h] + sup[h][d];
    }
}

// ---------------- combine partials across chunks ---------------------------
__global__ void combine_kernel() {
    int h  = blockIdx.x;
    int d0 = blockIdx.y * 32;
    int tid = threadIdx.x;
    int g  = tid >> 5;
    int dl = tid & 31;
    int d  = d0 + dl;

    __shared__ float sl[NCHUNK];
    sl[tid] = g_l[tid * NQ + h];
    __syncthreads();

    float acc = 0.f, L = 0.f;
#pragma unroll
    for (int k = 0; k < 32; k++) {
        int c = g * 32 + k;
        float l = sl[c];
        if (l > 0.f) {
            L += l;
            acc += g_part[(c * NQ + h) * HD + d];
        }
    }
    __shared__ float sacc[8][32];
    __shared__ float sLr[8][32];
    sacc[g][dl] = acc;
    sLr[g][dl]  = L;
    __syncthreads();
    if (g == 0) {
        float a = 0.f, Lt = 0.f;
#pragma unroll
        for (int k = 0; k < 8; k++) { a += sacc[k][dl]; Lt += sLr[k][dl]; }
        g_attn[h * HD + d] = a / Lt;
    }
}

// ---------------- launch ----------------------------------------------------
extern "C" void kernel_launch(void* const* d_in, const int* in_sizes, int n_in,
                              void* d_out, int out_size) {
    const float* hs   = (const float*)d_in[0];   // hidden_states (2048)
    const float* cosv = (const float*)d_in[1];   // cos (256)
    const float* sinv = (const float*)d_in[2];   // sin (256)
    const int*   kvix = (const int*)  d_in[3];   // kv_write_indices (1)
    const float* kc   = (const float*)d_in[4];   // k_cache
    const float* vc   = (const float*)d_in[5];   // v_cache
    const float* mask = (const float*)d_in[6];   // mask (8192)
    const float* qkvw = (const float*)d_in[7];   // qkv_w (2560x2048)
    const float* ow   = (const float*)d_in[8];   // o_w   (2048x2048)
    const float* qnw  = (const float*)d_in[9];   // q_norm_w (256)
    const float* knw  = (const float*)d_in[10];  // k_norm_w (256)
    float* out = (float*)d_out;

    void* p_qkv = nullptr;
    void* p_attn = nullptr;
    cudaGetSymbolAddress(&p_qkv, g_qkv);
    cudaGetSymbolAddress(&p_attn, g_attn);

    gemv_kernel<<<QKV_ROWS, 128>>>(qkvw, hs, (float*)p_qkv);
    fused_attn_kernel<<<NCHUNK, 512>>>(kc, vc, mask, cosv, sinv, qnw, knw, kvix);
    combine_kernel<<<dim3(NQ, 8), 256>>>();
    gemv_kernel<<<HIDDEN, 128>>>(ow, (const float*)p_attn, out);
}